// round 16
// baseline (speedup 1.0000x reference)
#include <cuda_runtime.h>
#include <cuda_bf16.h>
#include <cstdint>

#define N_NODES 100000
#define N_EDGES 1600000
#define IN_DIM 256
#define HID 128
#define N_GRAPHS 64
#define OUT_MF 489
#define OUT_BP 1943
#define OUT_CC 320

#define NPART 25                                  // ceil(100000/4096)
#define GEMM_BLOCKS ((N_NODES + 127) / 128)       // 782
#define EBLK4 ((N_EDGES / 4 + 255) / 256)         // 1563
#define EBLK8 ((N_EDGES / 8 + 255) / 256)         // 782
#define AGG_BLOCKS (N_NODES / 8)                  // 12500 (exact)

// ---------------- scratch (device globals; no runtime alloc) ----------------
__device__ __align__(16) __nv_bfloat16 g_h[N_NODES * HID];   // hs (scaled, bf16)
__device__ __align__(16) __nv_bfloat16 g_h2[N_NODES * HID];  // layer-1 activations (bf16)
__device__ float g_dis[N_NODES];
__device__ int   g_deg[N_NODES];
__device__ int   g_row_ptr[N_NODES + 1];
__device__ int   g_rank[N_EDGES];                 // per-edge rank within its dst row
__device__ int   g_col[N_EDGES];
__device__ int   g_part[NPART];
__device__ int   g_scan_arrive;                   // inter-block barrier counter
__device__ __align__(16) float g_pool[N_GRAPHS * HID];
__device__ int   g_cnt[N_GRAPHS];

// ---------------- zero init (graph-replay safe) ----------------
__global__ void k_zero() {
    int idx = blockIdx.x * blockDim.x + threadIdx.x;
    int stride = gridDim.x * blockDim.x;
    for (int i = idx; i < N_NODES; i += stride) g_deg[i] = 0;
    if (idx == 0) g_scan_arrive = 0;
}

// ---------------- in-degree count + rank capture (8 edges/thread) ----------------
__global__ void k_count(const int* __restrict__ dst) {
    int t = blockIdx.x * blockDim.x + threadIdx.x;
    int e = t * 8;
    if (e + 8 <= N_EDGES) {
        int4 d0 = *(const int4*)&dst[e];
        int4 d1 = *(const int4*)&dst[e + 4];
        int4 r0, r1;
        r0.x = atomicAdd(&g_deg[d0.x], 1);
        r0.y = atomicAdd(&g_deg[d0.y], 1);
        r0.z = atomicAdd(&g_deg[d0.z], 1);
        r0.w = atomicAdd(&g_deg[d0.w], 1);
        r1.x = atomicAdd(&g_deg[d1.x], 1);
        r1.y = atomicAdd(&g_deg[d1.y], 1);
        r1.z = atomicAdd(&g_deg[d1.z], 1);
        r1.w = atomicAdd(&g_deg[d1.w], 1);
        *(int4*)&g_rank[e] = r0;
        *(int4*)&g_rank[e + 4] = r1;
    } else {
        for (int i = e; i < N_EDGES; i++) g_rank[i] = atomicAdd(&g_deg[dst[i]], 1);
    }
}

// ---------------- fused scan: local scan -> inter-block barrier -> apply base -------
// 25 blocks, all co-resident => spin barrier deadlock-free. Offsets stay in registers.
__global__ void k_scan() {
    __shared__ int warp_sums[32];
    __shared__ int s_base;
    const int tid = threadIdx.x;
    const int lane = tid & 31;
    const int wid = tid >> 5;
    const int i0 = blockIdx.x * 4096 + tid * 4;

    // fold pool/cnt zero into this kernel's preamble
    {
        int gidx = blockIdx.x * 1024 + tid;
        if (gidx < N_GRAPHS * HID) g_pool[gidx] = 0.f;
        if (gidx < N_GRAPHS) g_cnt[gidx] = 0;
    }

    int v0 = (i0 + 0 < N_NODES) ? g_deg[i0 + 0] : 0;
    int v1 = (i0 + 1 < N_NODES) ? g_deg[i0 + 1] : 0;
    int v2 = (i0 + 2 < N_NODES) ? g_deg[i0 + 2] : 0;
    int v3 = (i0 + 3 < N_NODES) ? g_deg[i0 + 3] : 0;
    int t = v0 + v1 + v2 + v3;

    int x = t;
    #pragma unroll
    for (int s = 1; s < 32; s <<= 1) {
        int y = __shfl_up_sync(0xFFFFFFFFu, x, s);
        if (lane >= s) x += y;
    }
    if (lane == 31) warp_sums[wid] = x;
    __syncthreads();
    if (wid == 0) {
        int w = warp_sums[lane];
        #pragma unroll
        for (int s = 1; s < 32; s <<= 1) {
            int y = __shfl_up_sync(0xFFFFFFFFu, w, s);
            if (lane >= s) w += y;
        }
        warp_sums[lane] = w;
    }
    __syncthreads();

    int warp_excl = (wid == 0) ? 0 : warp_sums[wid - 1];
    int off = warp_excl + (x - t);      // block-local exclusive offset (registers)

    if (i0 + 0 < N_NODES) g_dis[i0 + 0] = rsqrtf((float)v0 + 1.0f);
    if (i0 + 1 < N_NODES) g_dis[i0 + 1] = rsqrtf((float)v1 + 1.0f);
    if (i0 + 2 < N_NODES) g_dis[i0 + 2] = rsqrtf((float)v2 + 1.0f);
    if (i0 + 3 < N_NODES) g_dis[i0 + 3] = rsqrtf((float)v3 + 1.0f);

    if (tid == 0) {
        g_part[blockIdx.x] = warp_sums[31];
        __threadfence();
        atomicAdd(&g_scan_arrive, 1);
        while (atomicAdd(&g_scan_arrive, 0) < NPART) __nanosleep(40);
        __threadfence();
        int b = 0, total = 0;
        #pragma unroll
        for (int p = 0; p < NPART; p++) {
            int v = *((volatile int*)&g_part[p]);
            if (p < (int)blockIdx.x) b += v;
            total += v;
        }
        s_base = b;
        if (blockIdx.x == 0) g_row_ptr[N_NODES] = total;
    }
    __syncthreads();

    int base = s_base;
    int e0 = base + off;
    int e1 = e0 + v0;
    int e2 = e1 + v1;
    int e3 = e2 + v2;
    if (i0 + 0 < N_NODES) g_row_ptr[i0 + 0] = e0;
    if (i0 + 1 < N_NODES) g_row_ptr[i0 + 1] = e1;
    if (i0 + 2 < N_NODES) g_row_ptr[i0 + 2] = e2;
    if (i0 + 3 < N_NODES) g_row_ptr[i0 + 3] = e3;
}

// ---------------- tf32 / mma / cp.async helpers ----------------
__device__ __forceinline__ uint32_t f2tf32(float v) {
    uint32_t u;
    asm("cvt.rna.tf32.f32 %0, %1;" : "=r"(u) : "f"(v));
    return u;
}
__device__ __forceinline__ uint32_t bits2tf32(uint32_t raw) {
    uint32_t u;
    asm("cvt.rna.tf32.f32 %0, %1;" : "=r"(u) : "f"(__uint_as_float(raw)));
    return u;
}
__device__ __forceinline__ void mma_tf32(float& c0, float& c1, float& c2, float& c3,
                                         uint32_t a0, uint32_t a1, uint32_t a2, uint32_t a3,
                                         uint32_t b0, uint32_t b1) {
    asm volatile(
        "mma.sync.aligned.m16n8k8.row.col.f32.tf32.tf32.f32 "
        "{%0,%1,%2,%3}, {%4,%5,%6,%7}, {%8,%9}, {%0,%1,%2,%3};"
        : "+f"(c0), "+f"(c1), "+f"(c2), "+f"(c3)
        : "r"(a0), "r"(a1), "r"(a2), "r"(a3), "r"(b0), "r"(b1));
}
__device__ __forceinline__ void cp_async16(uint32_t saddr, const void* gptr, int sz) {
    asm volatile("cp.async.ca.shared.global [%0], [%1], 16, %2;\n"
                 :: "r"(saddr), "l"(gptr), "r"(sz));
}
__device__ __forceinline__ void cp_commit() {
    asm volatile("cp.async.commit_group;\n" ::: "memory");
}
__device__ __forceinline__ void cp_wait0() {
    asm volatile("cp.async.wait_group 0;\n" ::: "memory");
}

// ---------------- GEMM1 body (fp32 A via cp.async): g_h = bf16((A@W)*dis) ------------
__device__ __forceinline__ void gemm1_body(const float* __restrict__ A,
                                           const float* __restrict__ W, int bid) {
    __shared__ uint32_t As[2][128 * 20];
    __shared__ uint32_t Wt[2][128 * 20];

    const int K = IN_DIM;
    const int tid = threadIdx.x;
    const int lane = tid & 31;
    const int wid = tid >> 5;
    const int warp_m = wid & 3;
    const int warp_n = wid >> 2;
    const int row0 = bid * 128;
    const int lq = lane >> 2;
    const int lr = lane & 3;

    const int ar0 = tid >> 2;
    const int ac0 = (tid & 3) * 4;
    const int ar1 = ar0 + 64;

    float4 wreg[2];

    auto load_A = [&](int stage, int kk) {
        {
            int row = row0 + ar0;
            uint32_t sa = (uint32_t)__cvta_generic_to_shared(&As[stage][ar0 * 20 + ac0]);
            cp_async16(sa, &A[(size_t)row * K + kk + ac0], (row < N_NODES) ? 16 : 0);
        }
        {
            int row = row0 + ar1;
            uint32_t sa = (uint32_t)__cvta_generic_to_shared(&As[stage][ar1 * 20 + ac0]);
            cp_async16(sa, &A[(size_t)row * K + kk + ac0], (row < N_NODES) ? 16 : 0);
        }
    };
    auto load_W_regs = [&](int kk) {
        #pragma unroll
        for (int j = 0; j < 2; j++) {
            int f = tid + 256 * j;
            int kr = f >> 5;
            int n4 = (f & 31) * 4;
            wreg[j] = *(const float4*)&W[(kk + kr) * HID + n4];
        }
    };
    auto store_W = [&](int stage) {
        #pragma unroll
        for (int j = 0; j < 2; j++) {
            int f = tid + 256 * j;
            int kr = f >> 5;
            int n4 = (f & 31) * 4;
            Wt[stage][(n4 + 0) * 20 + kr] = f2tf32(wreg[j].x);
            Wt[stage][(n4 + 1) * 20 + kr] = f2tf32(wreg[j].y);
            Wt[stage][(n4 + 2) * 20 + kr] = f2tf32(wreg[j].z);
            Wt[stage][(n4 + 3) * 20 + kr] = f2tf32(wreg[j].w);
        }
    };

    float acc[2][8][4];
    #pragma unroll
    for (int mt = 0; mt < 2; mt++)
        #pragma unroll
        for (int nt = 0; nt < 8; nt++)
            #pragma unroll
            for (int i = 0; i < 4; i++) acc[mt][nt][i] = 0.f;

    load_A(0, 0);
    cp_commit();
    load_W_regs(0);
    store_W(0);
    cp_wait0();
    __syncthreads();

    const int NT = K / 16;
    for (int t = 0; t < NT; t++) {
        int cur = t & 1;
        int nxt = cur ^ 1;
        if (t + 1 < NT) {
            load_A(nxt, (t + 1) * 16);
            cp_commit();
            load_W_regs((t + 1) * 16);
        }

        #pragma unroll
        for (int ks = 0; ks < 16; ks += 8) {
            uint32_t afr[2][4];
            #pragma unroll
            for (int mt = 0; mt < 2; mt++) {
                int rbase = (warp_m * 32 + mt * 16 + lq) * 20;
                afr[mt][0] = bits2tf32(As[cur][rbase + ks + lr]);
                afr[mt][1] = bits2tf32(As[cur][rbase + 8 * 20 + ks + lr]);
                afr[mt][2] = bits2tf32(As[cur][rbase + ks + 4 + lr]);
                afr[mt][3] = bits2tf32(As[cur][rbase + 8 * 20 + ks + 4 + lr]);
            }
            #pragma unroll
            for (int nt = 0; nt < 8; nt++) {
                int cbase = (warp_n * 64 + nt * 8 + lq) * 20;
                uint32_t b0 = Wt[cur][cbase + ks + lr];
                uint32_t b1 = Wt[cur][cbase + ks + 4 + lr];
                #pragma unroll
                for (int mt = 0; mt < 2; mt++) {
                    mma_tf32(acc[mt][nt][0], acc[mt][nt][1], acc[mt][nt][2], acc[mt][nt][3],
                             afr[mt][0], afr[mt][1], afr[mt][2], afr[mt][3], b0, b1);
                }
            }
        }

        if (t + 1 < NT) {
            store_W(nxt);
            cp_wait0();
            __syncthreads();
        }
    }

    #pragma unroll
    for (int mt = 0; mt < 2; mt++) {
        int r0 = row0 + warp_m * 32 + mt * 16 + lq;
        int r1 = r0 + 8;
        float d0 = (r0 < N_NODES) ? g_dis[r0] : 0.f;
        float d1 = (r1 < N_NODES) ? g_dis[r1] : 0.f;
        #pragma unroll
        for (int nt = 0; nt < 8; nt++) {
            int col = warp_n * 64 + nt * 8 + lr * 2;
            if (r0 < N_NODES) {
                __nv_bfloat162 o = __float22bfloat162_rn(
                    make_float2(acc[mt][nt][0] * d0, acc[mt][nt][1] * d0));
                *(__nv_bfloat162*)&g_h[r0 * HID + col] = o;
            }
            if (r1 < N_NODES) {
                __nv_bfloat162 o = __float22bfloat162_rn(
                    make_float2(acc[mt][nt][2] * d1, acc[mt][nt][3] * d1));
                *(__nv_bfloat162*)&g_h[r1 * HID + col] = o;
            }
        }
    }
}

// ---------------- mega: GEMM1 blocks || CSR-fill (atomic-free) blocks ----------------
__global__ void __launch_bounds__(256, 2) k_mega(const float* __restrict__ x,
                                                 const float* __restrict__ W1,
                                                 const int* __restrict__ src,
                                                 const int* __restrict__ dst) {
    if (blockIdx.x < GEMM_BLOCKS) {
        gemm1_body(x, W1, blockIdx.x);
        return;
    }
    // fill: slot = row_ptr[dst] + rank (no atomics)
    int t = (blockIdx.x - GEMM_BLOCKS) * blockDim.x + threadIdx.x;
    int e = t * 4;
    if (e + 4 <= N_EDGES) {
        int4 d = *(const int4*)&dst[e];
        int4 s = *(const int4*)&src[e];
        int4 r = *(const int4*)&g_rank[e];
        g_col[g_row_ptr[d.x] + r.x] = s.x;
        g_col[g_row_ptr[d.y] + r.y] = s.y;
        g_col[g_row_ptr[d.z] + r.z] = s.z;
        g_col[g_row_ptr[d.w] + r.w] = s.w;
    } else {
        for (int i = e; i < N_EDGES; i++)
            g_col[g_row_ptr[dst[i]] + g_rank[i]] = src[i];
    }
}

// ---------------- GEMM2: A = g_h2 (bf16, LDG->reg convert->STS pipeline) -------------
__global__ void __launch_bounds__(256, 2) k_gemm2(const float* __restrict__ W) {
    __shared__ uint32_t As[2][128 * 20];
    __shared__ uint32_t Wt[2][128 * 20];

    const int K = HID;
    const int tid = threadIdx.x;
    const int lane = tid & 31;
    const int wid = tid >> 5;
    const int warp_m = wid & 3;
    const int warp_n = wid >> 2;
    const int row0 = blockIdx.x * 128;
    const int lq = lane >> 2;
    const int lr = lane & 3;

    const int arow = tid >> 1;
    const int achk = (tid & 1) * 8;

    float4 wreg[2];
    uint4 areg;

    auto load_A_regs = [&](int kk) {
        int row = row0 + arow;
        if (row < N_NODES)
            areg = *(const uint4*)&g_h2[(size_t)row * K + kk + achk];
        else
            areg = make_uint4(0u, 0u, 0u, 0u);
    };
    auto store_A = [&](int stage) {
        uint32_t* dst = &As[stage][arow * 20 + achk];
        dst[0] = (areg.x & 0xFFFFu) << 16;
        dst[1] = (areg.x >> 16) << 16;
        dst[2] = (areg.y & 0xFFFFu) << 16;
        dst[3] = (areg.y >> 16) << 16;
        dst[4] = (areg.z & 0xFFFFu) << 16;
        dst[5] = (areg.z >> 16) << 16;
        dst[6] = (areg.w & 0xFFFFu) << 16;
        dst[7] = (areg.w >> 16) << 16;
    };
    auto load_W_regs = [&](int kk) {
        #pragma unroll
        for (int j = 0; j < 2; j++) {
            int f = tid + 256 * j;
            int kr = f >> 5;
            int n4 = (f & 31) * 4;
            wreg[j] = *(const float4*)&W[(kk + kr) * HID + n4];
        }
    };
    auto store_W = [&](int stage) {
        #pragma unroll
        for (int j = 0; j < 2; j++) {
            int f = tid + 256 * j;
            int kr = f >> 5;
            int n4 = (f & 31) * 4;
            Wt[stage][(n4 + 0) * 20 + kr] = f2tf32(wreg[j].x);
            Wt[stage][(n4 + 1) * 20 + kr] = f2tf32(wreg[j].y);
            Wt[stage][(n4 + 2) * 20 + kr] = f2tf32(wreg[j].z);
            Wt[stage][(n4 + 3) * 20 + kr] = f2tf32(wreg[j].w);
        }
    };

    float acc[2][8][4];
    #pragma unroll
    for (int mt = 0; mt < 2; mt++)
        #pragma unroll
        for (int nt = 0; nt < 8; nt++)
            #pragma unroll
            for (int i = 0; i < 4; i++) acc[mt][nt][i] = 0.f;

    load_A_regs(0);
    load_W_regs(0);
    store_A(0);
    store_W(0);
    __syncthreads();

    const int NT = K / 16;   // 8
    for (int t = 0; t < NT; t++) {
        int cur = t & 1;
        int nxt = cur ^ 1;
        if (t + 1 < NT) {
            load_A_regs((t + 1) * 16);
            load_W_regs((t + 1) * 16);
        }

        #pragma unroll
        for (int ks = 0; ks < 16; ks += 8) {
            uint32_t afr[2][4];
            #pragma unroll
            for (int mt = 0; mt < 2; mt++) {
                int rbase = (warp_m * 32 + mt * 16 + lq) * 20;
                afr[mt][0] = As[cur][rbase + ks + lr];
                afr[mt][1] = As[cur][rbase + 8 * 20 + ks + lr];
                afr[mt][2] = As[cur][rbase + ks + 4 + lr];
                afr[mt][3] = As[cur][rbase + 8 * 20 + ks + 4 + lr];
            }
            #pragma unroll
            for (int nt = 0; nt < 8; nt++) {
                int cbase = (warp_n * 64 + nt * 8 + lq) * 20;
                uint32_t b0 = Wt[cur][cbase + ks + lr];
                uint32_t b1 = Wt[cur][cbase + ks + 4 + lr];
                #pragma unroll
                for (int mt = 0; mt < 2; mt++) {
                    mma_tf32(acc[mt][nt][0], acc[mt][nt][1], acc[mt][nt][2], acc[mt][nt][3],
                             afr[mt][0], afr[mt][1], afr[mt][2], afr[mt][3], b0, b1);
                }
            }
        }

        if (t + 1 < NT) {
            __syncthreads();
            store_A(nxt);
            store_W(nxt);
            __syncthreads();
        }
    }

    #pragma unroll
    for (int mt = 0; mt < 2; mt++) {
        int r0 = row0 + warp_m * 32 + mt * 16 + lq;
        int r1 = r0 + 8;
        float d0 = (r0 < N_NODES) ? g_dis[r0] : 0.f;
        float d1 = (r1 < N_NODES) ? g_dis[r1] : 0.f;
        #pragma unroll
        for (int nt = 0; nt < 8; nt++) {
            int col = warp_n * 64 + nt * 8 + lr * 2;
            if (r0 < N_NODES) {
                __nv_bfloat162 o = __float22bfloat162_rn(
                    make_float2(acc[mt][nt][0] * d0, acc[mt][nt][1] * d0));
                *(__nv_bfloat162*)&g_h[r0 * HID + col] = o;
            }
            if (r1 < N_NODES) {
                __nv_bfloat162 o = __float22bfloat162_rn(
                    make_float2(acc[mt][nt][2] * d1, acc[mt][nt][3] * d1));
                *(__nv_bfloat162*)&g_h[r1 * HID + col] = o;
            }
        }
    }
}

// ---------------- edge aggregation (pull, warp/node, bf16 uint2 gather) ----------
__device__ __forceinline__ void acc_bf16x4(float4& a, uint2 v) {
    float2 f0 = __bfloat1622float2(*(const __nv_bfloat162*)&v.x);
    float2 f1 = __bfloat1622float2(*(const __nv_bfloat162*)&v.y);
    a.x += f0.x; a.y += f0.y; a.z += f1.x; a.w += f1.y;
}

template <bool POOL>
__global__ void k_agg(const float* __restrict__ bias, const int* __restrict__ batch) {
    __shared__ float s_row[8][128];
    __shared__ int s_b[8];

    int node = (blockIdx.x * blockDim.x + threadIdx.x) >> 5;  // exact grid
    int lane = threadIdx.x & 31;
    int w = threadIdx.x >> 5;

    const uint2* hs = (const uint2*)g_h;
    int beg = g_row_ptr[node];
    int end = g_row_ptr[node + 1];

    float4 a0 = make_float4(0.f, 0.f, 0.f, 0.f);
    float4 a1 = make_float4(0.f, 0.f, 0.f, 0.f);
    float4 a2 = make_float4(0.f, 0.f, 0.f, 0.f);
    float4 a3 = make_float4(0.f, 0.f, 0.f, 0.f);
    acc_bf16x4(a0, hs[node * 32 + lane]);  // self (pre-scaled)

    int e = beg;
    for (; e + 8 <= end; e += 8) {
        int s0 = g_col[e + 0];
        int s1 = g_col[e + 1];
        int s2 = g_col[e + 2];
        int s3 = g_col[e + 3];
        int s4 = g_col[e + 4];
        int s5 = g_col[e + 5];
        int s6 = g_col[e + 6];
        int s7 = g_col[e + 7];
        uint2 v0 = hs[s0 * 32 + lane];
        uint2 v1 = hs[s1 * 32 + lane];
        uint2 v2 = hs[s2 * 32 + lane];
        uint2 v3 = hs[s3 * 32 + lane];
        uint2 v4 = hs[s4 * 32 + lane];
        uint2 v5 = hs[s5 * 32 + lane];
        uint2 v6 = hs[s6 * 32 + lane];
        uint2 v7 = hs[s7 * 32 + lane];
        acc_bf16x4(a0, v0);
        acc_bf16x4(a1, v1);
        acc_bf16x4(a2, v2);
        acc_bf16x4(a3, v3);
        acc_bf16x4(a0, v4);
        acc_bf16x4(a1, v5);
        acc_bf16x4(a2, v6);
        acc_bf16x4(a3, v7);
    }
    for (; e + 4 <= end; e += 4) {
        int s0 = g_col[e + 0];
        int s1 = g_col[e + 1];
        int s2 = g_col[e + 2];
        int s3 = g_col[e + 3];
        uint2 v0 = hs[s0 * 32 + lane];
        uint2 v1 = hs[s1 * 32 + lane];
        uint2 v2 = hs[s2 * 32 + lane];
        uint2 v3 = hs[s3 * 32 + lane];
        acc_bf16x4(a0, v0);
        acc_bf16x4(a1, v1);
        acc_bf16x4(a2, v2);
        acc_bf16x4(a3, v3);
    }
    for (; e < end; e++) {
        acc_bf16x4(a0, hs[g_col[e] * 32 + lane]);
    }
    a0.x += a1.x + a2.x + a3.x;
    a0.y += a1.y + a2.y + a3.y;
    a0.z += a1.z + a2.z + a3.z;
    a0.w += a1.w + a2.w + a3.w;

    float d = g_dis[node];
    float4 bb = ((const float4*)bias)[lane];
    float4 r;
    r.x = fmaxf(fmaf(d, a0.x, bb.x), 0.f);
    r.y = fmaxf(fmaf(d, a0.y, bb.y), 0.f);
    r.z = fmaxf(fmaf(d, a0.z, bb.z), 0.f);
    r.w = fmaxf(fmaf(d, a0.w, bb.w), 0.f);

    if (!POOL) {
        __nv_bfloat162 o0 = __float22bfloat162_rn(make_float2(r.x, r.y));
        __nv_bfloat162 o1 = __float22bfloat162_rn(make_float2(r.z, r.w));
        uint2 ov;
        ov.x = *(const uint32_t*)&o0;
        ov.y = *(const uint32_t*)&o1;
        ((uint2*)g_h2)[node * 32 + lane] = ov;
    } else {
        ((float4*)s_row[w])[lane] = r;
        if (lane == 0) s_b[w] = batch[node];
        __syncthreads();
        if (threadIdx.x < 128) {
            int col = threadIdx.x;
            float acc = 0.f;
            int cnt = 0;
            int cur = s_b[0];
            #pragma unroll
            for (int n = 0; n < 8; n++) {
                int g = s_b[n];
                if (g != cur) {
                    atomicAdd(&g_pool[cur * HID + col], acc);
                    if (col == 0) atomicAdd(&g_cnt[cur], cnt);
                    acc = 0.f; cnt = 0; cur = g;
                }
                acc += s_row[n][col];
                cnt++;
            }
            atomicAdd(&g_pool[cur * HID + col], acc);
            if (col == 0) atomicAdd(&g_cnt[cur], cnt);
        }
    }
}

// ---------------- output heads (mean-div fused) ----------------
__global__ void k_heads(const float* __restrict__ Wmf, const float* __restrict__ bmf,
                        const float* __restrict__ Wbp, const float* __restrict__ bbp,
                        const float* __restrict__ Wcc, const float* __restrict__ bcc,
                        float* __restrict__ out) {
    const int TOT = OUT_MF + OUT_BP + OUT_CC;
    int idx = blockIdx.x * blockDim.x + threadIdx.x;
    if (idx >= N_GRAPHS * TOT) return;
    int g = idx / TOT;
    int c = idx % TOT;

    const float* W;
    const float* b;
    float* o;
    int od, cc;
    if (c < OUT_MF) {
        W = Wmf; b = bmf; od = OUT_MF; cc = c;
        o = out;
    } else if (c < OUT_MF + OUT_BP) {
        W = Wbp; b = bbp; od = OUT_BP; cc = c - OUT_MF;
        o = out + N_GRAPHS * OUT_MF;
    } else {
        W = Wcc; b = bcc; od = OUT_CC; cc = c - OUT_MF - OUT_BP;
        o = out + N_GRAPHS * (OUT_MF + OUT_BP);
    }

    const float* p = g_pool + g * HID;
    float inv = 1.0f / fmaxf((float)g_cnt[g], 1.0f);
    float acc = 0.f;
    #pragma unroll 8
    for (int k = 0; k < HID; k++) acc = fmaf(p[k], W[k * od + cc], acc);
    o[g * od + cc] = fmaf(acc, inv, b[cc]);
}

// ---------------- launch (single stream, capture-safe) ----------------
extern "C" void kernel_launch(void* const* d_in, const int* in_sizes, int n_in,
                              void* d_out, int out_size) {
    const float* x    = (const float*)d_in[0];
    const int*   ei   = (const int*)d_in[1];
    const int*   bat  = (const int*)d_in[2];
    const float* W1   = (const float*)d_in[3];
    const float* b1   = (const float*)d_in[4];
    const float* W2   = (const float*)d_in[5];
    const float* b2   = (const float*)d_in[6];
    const float* Wmf  = (const float*)d_in[7];
    const float* bmf  = (const float*)d_in[8];
    const float* Wbp  = (const float*)d_in[9];
    const float* bbp  = (const float*)d_in[10];
    const float* Wcc  = (const float*)d_in[11];
    const float* bcc  = (const float*)d_in[12];
    float* out = (float*)d_out;

    const int* src = ei;
    const int* dst = ei + N_EDGES;

    // CSR prep (count captures per-edge rank; fused scan)
    k_zero<<<512, 256>>>();
    k_count<<<EBLK8, 256>>>(dst);
    k_scan<<<NPART, 1024>>>();

    // GEMM1 (dis epilogue, writes scaled bf16 hs) || atomic-free CSR fill
    k_mega<<<GEMM_BLOCKS + EBLK4, 256>>>(x, W1, src, dst);

    // layer 1 aggregation (writes bf16 h2)
    k_agg<false><<<AGG_BLOCKS, 256>>>(b1, bat);

    // layer 2
    k_gemm2<<<GEMM_BLOCKS, 256>>>(W2);
    k_agg<true><<<AGG_BLOCKS, 256>>>(b2, bat);           // agg + fused pooling

    k_heads<<<(N_GRAPHS * (OUT_MF + OUT_BP + OUT_CC) + 255) / 256, 256>>>(
        Wmf, bmf, Wbp, bbp, Wcc, bcc, out);
}

// round 17
// speedup vs baseline: 1.2451x; 1.2451x over previous
#include <cuda_runtime.h>
#include <cuda_bf16.h>
#include <cstdint>

#define N_NODES 100000
#define N_EDGES 1600000
#define IN_DIM 256
#define HID 128
#define N_GRAPHS 64
#define OUT_MF 489
#define OUT_BP 1943
#define OUT_CC 320

#define NPART 25                                  // ceil(100000/4096)
#define GEMM_BLOCKS ((N_NODES + 127) / 128)       // 782
#define EBLK4 ((N_EDGES / 4 + 255) / 256)         // 1563
#define EBLK8 ((N_EDGES / 8 + 255) / 256)         // 782
#define AGG_BLOCKS (N_NODES / 8)                  // 12500 (exact)

#define WSTRIDE 136                               // W smem row stride (k-major), conflict-free

// ---------------- scratch (device globals; no runtime alloc) ----------------
__device__ __align__(16) __nv_bfloat16 g_h[N_NODES * HID];   // hs (scaled, bf16)
__device__ __align__(16) __nv_bfloat16 g_h2[N_NODES * HID];  // layer-1 activations (bf16)
__device__ float g_dis[N_NODES];
__device__ int   g_deg[N_NODES];
__device__ int   g_row_ptr[N_NODES + 1];
__device__ int   g_rank[N_EDGES];                 // per-edge rank within its dst row
__device__ int   g_col[N_EDGES];
__device__ int   g_part[NPART];
__device__ int   g_scan_arrive;                   // inter-block barrier counter
__device__ __align__(16) float g_pool[N_GRAPHS * HID];
__device__ int   g_cnt[N_GRAPHS];

// ---------------- zero init (graph-replay safe) ----------------
__global__ void k_zero() {
    int idx = blockIdx.x * blockDim.x + threadIdx.x;
    int stride = gridDim.x * blockDim.x;
    for (int i = idx; i < N_NODES; i += stride) g_deg[i] = 0;
    if (idx == 0) g_scan_arrive = 0;
}

// ---------------- in-degree count + rank capture (8 edges/thread) ----------------
__global__ void k_count(const int* __restrict__ dst) {
    int t = blockIdx.x * blockDim.x + threadIdx.x;
    int e = t * 8;
    if (e + 8 <= N_EDGES) {
        int4 d0 = *(const int4*)&dst[e];
        int4 d1 = *(const int4*)&dst[e + 4];
        int4 r0, r1;
        r0.x = atomicAdd(&g_deg[d0.x], 1);
        r0.y = atomicAdd(&g_deg[d0.y], 1);
        r0.z = atomicAdd(&g_deg[d0.z], 1);
        r0.w = atomicAdd(&g_deg[d0.w], 1);
        r1.x = atomicAdd(&g_deg[d1.x], 1);
        r1.y = atomicAdd(&g_deg[d1.y], 1);
        r1.z = atomicAdd(&g_deg[d1.z], 1);
        r1.w = atomicAdd(&g_deg[d1.w], 1);
        *(int4*)&g_rank[e] = r0;
        *(int4*)&g_rank[e + 4] = r1;
    } else {
        for (int i = e; i < N_EDGES; i++) g_rank[i] = atomicAdd(&g_deg[dst[i]], 1);
    }
}

// ---------------- fused scan: local scan -> inter-block barrier -> apply base -------
__global__ void k_scan() {
    __shared__ int warp_sums[32];
    __shared__ int s_base;
    const int tid = threadIdx.x;
    const int lane = tid & 31;
    const int wid = tid >> 5;
    const int i0 = blockIdx.x * 4096 + tid * 4;

    {
        int gidx = blockIdx.x * 1024 + tid;
        if (gidx < N_GRAPHS * HID) g_pool[gidx] = 0.f;
        if (gidx < N_GRAPHS) g_cnt[gidx] = 0;
    }

    int v0 = (i0 + 0 < N_NODES) ? g_deg[i0 + 0] : 0;
    int v1 = (i0 + 1 < N_NODES) ? g_deg[i0 + 1] : 0;
    int v2 = (i0 + 2 < N_NODES) ? g_deg[i0 + 2] : 0;
    int v3 = (i0 + 3 < N_NODES) ? g_deg[i0 + 3] : 0;
    int t = v0 + v1 + v2 + v3;

    int x = t;
    #pragma unroll
    for (int s = 1; s < 32; s <<= 1) {
        int y = __shfl_up_sync(0xFFFFFFFFu, x, s);
        if (lane >= s) x += y;
    }
    if (lane == 31) warp_sums[wid] = x;
    __syncthreads();
    if (wid == 0) {
        int w = warp_sums[lane];
        #pragma unroll
        for (int s = 1; s < 32; s <<= 1) {
            int y = __shfl_up_sync(0xFFFFFFFFu, w, s);
            if (lane >= s) w += y;
        }
        warp_sums[lane] = w;
    }
    __syncthreads();

    int warp_excl = (wid == 0) ? 0 : warp_sums[wid - 1];
    int off = warp_excl + (x - t);

    if (i0 + 0 < N_NODES) g_dis[i0 + 0] = rsqrtf((float)v0 + 1.0f);
    if (i0 + 1 < N_NODES) g_dis[i0 + 1] = rsqrtf((float)v1 + 1.0f);
    if (i0 + 2 < N_NODES) g_dis[i0 + 2] = rsqrtf((float)v2 + 1.0f);
    if (i0 + 3 < N_NODES) g_dis[i0 + 3] = rsqrtf((float)v3 + 1.0f);

    if (tid == 0) {
        g_part[blockIdx.x] = warp_sums[31];
        __threadfence();
        atomicAdd(&g_scan_arrive, 1);
        while (atomicAdd(&g_scan_arrive, 0) < NPART) __nanosleep(40);
        __threadfence();
        int b = 0, total = 0;
        #pragma unroll
        for (int p = 0; p < NPART; p++) {
            int v = *((volatile int*)&g_part[p]);
            if (p < (int)blockIdx.x) b += v;
            total += v;
        }
        s_base = b;
        if (blockIdx.x == 0) g_row_ptr[N_NODES] = total;
    }
    __syncthreads();

    int base = s_base;
    int e0 = base + off;
    int e1 = e0 + v0;
    int e2 = e1 + v1;
    int e3 = e2 + v2;
    if (i0 + 0 < N_NODES) g_row_ptr[i0 + 0] = e0;
    if (i0 + 1 < N_NODES) g_row_ptr[i0 + 1] = e1;
    if (i0 + 2 < N_NODES) g_row_ptr[i0 + 2] = e2;
    if (i0 + 3 < N_NODES) g_row_ptr[i0 + 3] = e3;
}

// ---------------- tf32 / mma / cp.async helpers ----------------
__device__ __forceinline__ uint32_t f2tf32(float v) {
    uint32_t u;
    asm("cvt.rna.tf32.f32 %0, %1;" : "=r"(u) : "f"(v));
    return u;
}
__device__ __forceinline__ uint32_t bits2tf32(uint32_t raw) {
    uint32_t u;
    asm("cvt.rna.tf32.f32 %0, %1;" : "=r"(u) : "f"(__uint_as_float(raw)));
    return u;
}
__device__ __forceinline__ void mma_tf32(float& c0, float& c1, float& c2, float& c3,
                                         uint32_t a0, uint32_t a1, uint32_t a2, uint32_t a3,
                                         uint32_t b0, uint32_t b1) {
    asm volatile(
        "mma.sync.aligned.m16n8k8.row.col.f32.tf32.tf32.f32 "
        "{%0,%1,%2,%3}, {%4,%5,%6,%7}, {%8,%9}, {%0,%1,%2,%3};"
        : "+f"(c0), "+f"(c1), "+f"(c2), "+f"(c3)
        : "r"(a0), "r"(a1), "r"(a2), "r"(a3), "r"(b0), "r"(b1));
}
// .cg: L2-only (bypass L1 allocate) — A stream has zero reuse
__device__ __forceinline__ void cp_async16_cg(uint32_t saddr, const void* gptr, int sz) {
    asm volatile("cp.async.cg.shared.global [%0], [%1], 16, %2;\n"
                 :: "r"(saddr), "l"(gptr), "r"(sz));
}
__device__ __forceinline__ void cp_commit() {
    asm volatile("cp.async.commit_group;\n" ::: "memory");
}
__device__ __forceinline__ void cp_wait0() {
    asm volatile("cp.async.wait_group 0;\n" ::: "memory");
}

// ---------------- GEMM1 body (fp32 A via cp.async.cg): g_h = bf16((A@W)*dis) ---------
// W smem is k-major [16][WSTRIDE]: STS.128 conflict-free store, conflict-free frag LDS.
__device__ __forceinline__ void gemm1_body(const float* __restrict__ A,
                                           const float* __restrict__ W, int bid) {
    __shared__ uint32_t As[2][128 * 20];
    __shared__ __align__(16) uint32_t Wt[2][16 * WSTRIDE];

    const int K = IN_DIM;
    const int tid = threadIdx.x;
    const int lane = tid & 31;
    const int wid = tid >> 5;
    const int warp_m = wid & 3;
    const int warp_n = wid >> 2;
    const int row0 = bid * 128;
    const int lq = lane >> 2;
    const int lr = lane & 3;

    const int ar0 = tid >> 2;
    const int ac0 = (tid & 3) * 4;
    const int ar1 = ar0 + 64;

    float4 wreg[2];

    auto load_A = [&](int stage, int kk) {
        {
            int row = row0 + ar0;
            uint32_t sa = (uint32_t)__cvta_generic_to_shared(&As[stage][ar0 * 20 + ac0]);
            cp_async16_cg(sa, &A[(size_t)row * K + kk + ac0], (row < N_NODES) ? 16 : 0);
        }
        {
            int row = row0 + ar1;
            uint32_t sa = (uint32_t)__cvta_generic_to_shared(&As[stage][ar1 * 20 + ac0]);
            cp_async16_cg(sa, &A[(size_t)row * K + kk + ac0], (row < N_NODES) ? 16 : 0);
        }
    };
    auto load_W_regs = [&](int kk) {
        #pragma unroll
        for (int j = 0; j < 2; j++) {
            int f = tid + 256 * j;
            int kr = f >> 5;
            int n4 = (f & 31) * 4;
            wreg[j] = *(const float4*)&W[(kk + kr) * HID + n4];
        }
    };
    auto store_W = [&](int stage) {
        #pragma unroll
        for (int j = 0; j < 2; j++) {
            int f = tid + 256 * j;
            int kr = f >> 5;
            int n4 = (f & 31) * 4;
            uint4 o;
            o.x = f2tf32(wreg[j].x);
            o.y = f2tf32(wreg[j].y);
            o.z = f2tf32(wreg[j].z);
            o.w = f2tf32(wreg[j].w);
            *(uint4*)&Wt[stage][kr * WSTRIDE + n4] = o;  // STS.128, conflict-free
        }
    };

    float acc[2][8][4];
    #pragma unroll
    for (int mt = 0; mt < 2; mt++)
        #pragma unroll
        for (int nt = 0; nt < 8; nt++)
            #pragma unroll
            for (int i = 0; i < 4; i++) acc[mt][nt][i] = 0.f;

    load_A(0, 0);
    cp_commit();
    load_W_regs(0);
    store_W(0);
    cp_wait0();
    __syncthreads();

    const int NT = K / 16;
    for (int t = 0; t < NT; t++) {
        int cur = t & 1;
        int nxt = cur ^ 1;
        if (t + 1 < NT) {
            load_A(nxt, (t + 1) * 16);
            cp_commit();
            load_W_regs((t + 1) * 16);
        }

        #pragma unroll
        for (int ks = 0; ks < 16; ks += 8) {
            uint32_t afr[2][4];
            #pragma unroll
            for (int mt = 0; mt < 2; mt++) {
                int rbase = (warp_m * 32 + mt * 16 + lq) * 20;
                afr[mt][0] = bits2tf32(As[cur][rbase + ks + lr]);
                afr[mt][1] = bits2tf32(As[cur][rbase + 8 * 20 + ks + lr]);
                afr[mt][2] = bits2tf32(As[cur][rbase + ks + 4 + lr]);
                afr[mt][3] = bits2tf32(As[cur][rbase + 8 * 20 + ks + 4 + lr]);
            }
            #pragma unroll
            for (int nt = 0; nt < 8; nt++) {
                int coln = warp_n * 64 + nt * 8 + lq;
                uint32_t b0 = Wt[cur][(ks + lr) * WSTRIDE + coln];
                uint32_t b1 = Wt[cur][(ks + 4 + lr) * WSTRIDE + coln];
                #pragma unroll
                for (int mt = 0; mt < 2; mt++) {
                    mma_tf32(acc[mt][nt][0], acc[mt][nt][1], acc[mt][nt][2], acc[mt][nt][3],
                             afr[mt][0], afr[mt][1], afr[mt][2], afr[mt][3], b0, b1);
                }
            }
        }

        if (t + 1 < NT) {
            store_W(nxt);
            cp_wait0();
            __syncthreads();
        }
    }

    #pragma unroll
    for (int mt = 0; mt < 2; mt++) {
        int r0 = row0 + warp_m * 32 + mt * 16 + lq;
        int r1 = r0 + 8;
        float d0 = (r0 < N_NODES) ? g_dis[r0] : 0.f;
        float d1 = (r1 < N_NODES) ? g_dis[r1] : 0.f;
        #pragma unroll
        for (int nt = 0; nt < 8; nt++) {
            int col = warp_n * 64 + nt * 8 + lr * 2;
            if (r0 < N_NODES) {
                __nv_bfloat162 o = __float22bfloat162_rn(
                    make_float2(acc[mt][nt][0] * d0, acc[mt][nt][1] * d0));
                *(__nv_bfloat162*)&g_h[r0 * HID + col] = o;
            }
            if (r1 < N_NODES) {
                __nv_bfloat162 o = __float22bfloat162_rn(
                    make_float2(acc[mt][nt][2] * d1, acc[mt][nt][3] * d1));
                *(__nv_bfloat162*)&g_h[r1 * HID + col] = o;
            }
        }
    }
}

// ---------------- mega: GEMM1 blocks || CSR-fill (atomic-free) blocks ----------------
__global__ void __launch_bounds__(256, 2) k_mega(const float* __restrict__ x,
                                                 const float* __restrict__ W1,
                                                 const int* __restrict__ src,
                                                 const int* __restrict__ dst) {
    if (blockIdx.x < GEMM_BLOCKS) {
        gemm1_body(x, W1, blockIdx.x);
        return;
    }
    int t = (blockIdx.x - GEMM_BLOCKS) * blockDim.x + threadIdx.x;
    int e = t * 4;
    if (e + 4 <= N_EDGES) {
        int4 d = *(const int4*)&dst[e];
        int4 s = *(const int4*)&src[e];
        int4 r = *(const int4*)&g_rank[e];
        g_col[g_row_ptr[d.x] + r.x] = s.x;
        g_col[g_row_ptr[d.y] + r.y] = s.y;
        g_col[g_row_ptr[d.z] + r.z] = s.z;
        g_col[g_row_ptr[d.w] + r.w] = s.w;
    } else {
        for (int i = e; i < N_EDGES; i++)
            g_col[g_row_ptr[dst[i]] + g_rank[i]] = src[i];
    }
}

// ---------------- GEMM2: A = g_h2 (bf16, LDG->reg convert->STS pipeline) -------------
__global__ void __launch_bounds__(256, 2) k_gemm2(const float* __restrict__ W) {
    __shared__ uint32_t As[2][128 * 20];
    __shared__ __align__(16) uint32_t Wt[2][16 * WSTRIDE];

    const int K = HID;
    const int tid = threadIdx.x;
    const int lane = tid & 31;
    const int wid = tid >> 5;
    const int warp_m = wid & 3;
    const int warp_n = wid >> 2;
    const int row0 = blockIdx.x * 128;
    const int lq = lane >> 2;
    const int lr = lane & 3;

    const int arow = tid >> 1;
    const int achk = (tid & 1) * 8;

    float4 wreg[2];
    uint4 areg;

    auto load_A_regs = [&](int kk) {
        int row = row0 + arow;
        if (row < N_NODES)
            areg = *(const uint4*)&g_h2[(size_t)row * K + kk + achk];
        else
            areg = make_uint4(0u, 0u, 0u, 0u);
    };
    auto store_A = [&](int stage) {
        uint32_t* dst = &As[stage][arow * 20 + achk];
        dst[0] = (areg.x & 0xFFFFu) << 16;
        dst[1] = (areg.x >> 16) << 16;
        dst[2] = (areg.y & 0xFFFFu) << 16;
        dst[3] = (areg.y >> 16) << 16;
        dst[4] = (areg.z & 0xFFFFu) << 16;
        dst[5] = (areg.z >> 16) << 16;
        dst[6] = (areg.w & 0xFFFFu) << 16;
        dst[7] = (areg.w >> 16) << 16;
    };
    auto load_W_regs = [&](int kk) {
        #pragma unroll
        for (int j = 0; j < 2; j++) {
            int f = tid + 256 * j;
            int kr = f >> 5;
            int n4 = (f & 31) * 4;
            wreg[j] = *(const float4*)&W[(kk + kr) * HID + n4];
        }
    };
    auto store_W = [&](int stage) {
        #pragma unroll
        for (int j = 0; j < 2; j++) {
            int f = tid + 256 * j;
            int kr = f >> 5;
            int n4 = (f & 31) * 4;
            uint4 o;
            o.x = f2tf32(wreg[j].x);
            o.y = f2tf32(wreg[j].y);
            o.z = f2tf32(wreg[j].z);
            o.w = f2tf32(wreg[j].w);
            *(uint4*)&Wt[stage][kr * WSTRIDE + n4] = o;  // STS.128, conflict-free
        }
    };

    float acc[2][8][4];
    #pragma unroll
    for (int mt = 0; mt < 2; mt++)
        #pragma unroll
        for (int nt = 0; nt < 8; nt++)
            #pragma unroll
            for (int i = 0; i < 4; i++) acc[mt][nt][i] = 0.f;

    load_A_regs(0);
    load_W_regs(0);
    store_A(0);
    store_W(0);
    __syncthreads();

    const int NT = K / 16;   // 8
    for (int t = 0; t < NT; t++) {
        int cur = t & 1;
        int nxt = cur ^ 1;
        if (t + 1 < NT) {
            load_A_regs((t + 1) * 16);
            load_W_regs((t + 1) * 16);
        }

        #pragma unroll
        for (int ks = 0; ks < 16; ks += 8) {
            uint32_t afr[2][4];
            #pragma unroll
            for (int mt = 0; mt < 2; mt++) {
                int rbase = (warp_m * 32 + mt * 16 + lq) * 20;
                afr[mt][0] = As[cur][rbase + ks + lr];
                afr[mt][1] = As[cur][rbase + 8 * 20 + ks + lr];
                afr[mt][2] = As[cur][rbase + ks + 4 + lr];
                afr[mt][3] = As[cur][rbase + 8 * 20 + ks + 4 + lr];
            }
            #pragma unroll
            for (int nt = 0; nt < 8; nt++) {
                int coln = warp_n * 64 + nt * 8 + lq;
                uint32_t b0 = Wt[cur][(ks + lr) * WSTRIDE + coln];
                uint32_t b1 = Wt[cur][(ks + 4 + lr) * WSTRIDE + coln];
                #pragma unroll
                for (int mt = 0; mt < 2; mt++) {
                    mma_tf32(acc[mt][nt][0], acc[mt][nt][1], acc[mt][nt][2], acc[mt][nt][3],
                             afr[mt][0], afr[mt][1], afr[mt][2], afr[mt][3], b0, b1);
                }
            }
        }

        if (t + 1 < NT) {
            __syncthreads();
            store_A(nxt);
            store_W(nxt);
            __syncthreads();
        }
    }

    #pragma unroll
    for (int mt = 0; mt < 2; mt++) {
        int r0 = row0 + warp_m * 32 + mt * 16 + lq;
        int r1 = r0 + 8;
        float d0 = (r0 < N_NODES) ? g_dis[r0] : 0.f;
        float d1 = (r1 < N_NODES) ? g_dis[r1] : 0.f;
        #pragma unroll
        for (int nt = 0; nt < 8; nt++) {
            int col = warp_n * 64 + nt * 8 + lr * 2;
            if (r0 < N_NODES) {
                __nv_bfloat162 o = __float22bfloat162_rn(
                    make_float2(acc[mt][nt][0] * d0, acc[mt][nt][1] * d0));
                *(__nv_bfloat162*)&g_h[r0 * HID + col] = o;
            }
            if (r1 < N_NODES) {
                __nv_bfloat162 o = __float22bfloat162_rn(
                    make_float2(acc[mt][nt][2] * d1, acc[mt][nt][3] * d1));
                *(__nv_bfloat162*)&g_h[r1 * HID + col] = o;
            }
        }
    }
}

// ---------------- edge aggregation (pull, warp/node, bf16 uint2 gather) ----------
__device__ __forceinline__ void acc_bf16x4(float4& a, uint2 v) {
    float2 f0 = __bfloat1622float2(*(const __nv_bfloat162*)&v.x);
    float2 f1 = __bfloat1622float2(*(const __nv_bfloat162*)&v.y);
    a.x += f0.x; a.y += f0.y; a.z += f1.x; a.w += f1.y;
}

template <bool POOL>
__global__ void k_agg(const float* __restrict__ bias, const int* __restrict__ batch) {
    __shared__ float s_row[8][128];
    __shared__ int s_b[8];

    int node = (blockIdx.x * blockDim.x + threadIdx.x) >> 5;  // exact grid
    int lane = threadIdx.x & 31;
    int w = threadIdx.x >> 5;

    const uint2* hs = (const uint2*)g_h;
    int beg = g_row_ptr[node];
    int end = g_row_ptr[node + 1];

    float4 a0 = make_float4(0.f, 0.f, 0.f, 0.f);
    float4 a1 = make_float4(0.f, 0.f, 0.f, 0.f);
    float4 a2 = make_float4(0.f, 0.f, 0.f, 0.f);
    float4 a3 = make_float4(0.f, 0.f, 0.f, 0.f);
    acc_bf16x4(a0, hs[node * 32 + lane]);  // self (pre-scaled)

    int e = beg;
    for (; e + 8 <= end; e += 8) {
        int s0 = g_col[e + 0];
        int s1 = g_col[e + 1];
        int s2 = g_col[e + 2];
        int s3 = g_col[e + 3];
        int s4 = g_col[e + 4];
        int s5 = g_col[e + 5];
        int s6 = g_col[e + 6];
        int s7 = g_col[e + 7];
        uint2 v0 = hs[s0 * 32 + lane];
        uint2 v1 = hs[s1 * 32 + lane];
        uint2 v2 = hs[s2 * 32 + lane];
        uint2 v3 = hs[s3 * 32 + lane];
        uint2 v4 = hs[s4 * 32 + lane];
        uint2 v5 = hs[s5 * 32 + lane];
        uint2 v6 = hs[s6 * 32 + lane];
        uint2 v7 = hs[s7 * 32 + lane];
        acc_bf16x4(a0, v0);
        acc_bf16x4(a1, v1);
        acc_bf16x4(a2, v2);
        acc_bf16x4(a3, v3);
        acc_bf16x4(a0, v4);
        acc_bf16x4(a1, v5);
        acc_bf16x4(a2, v6);
        acc_bf16x4(a3, v7);
    }
    for (; e + 4 <= end; e += 4) {
        int s0 = g_col[e + 0];
        int s1 = g_col[e + 1];
        int s2 = g_col[e + 2];
        int s3 = g_col[e + 3];
        uint2 v0 = hs[s0 * 32 + lane];
        uint2 v1 = hs[s1 * 32 + lane];
        uint2 v2 = hs[s2 * 32 + lane];
        uint2 v3 = hs[s3 * 32 + lane];
        acc_bf16x4(a0, v0);
        acc_bf16x4(a1, v1);
        acc_bf16x4(a2, v2);
        acc_bf16x4(a3, v3);
    }
    for (; e < end; e++) {
        acc_bf16x4(a0, hs[g_col[e] * 32 + lane]);
    }
    a0.x += a1.x + a2.x + a3.x;
    a0.y += a1.y + a2.y + a3.y;
    a0.z += a1.z + a2.z + a3.z;
    a0.w += a1.w + a2.w + a3.w;

    float d = g_dis[node];
    float4 bb = ((const float4*)bias)[lane];
    float4 r;
    r.x = fmaxf(fmaf(d, a0.x, bb.x), 0.f);
    r.y = fmaxf(fmaf(d, a0.y, bb.y), 0.f);
    r.z = fmaxf(fmaf(d, a0.z, bb.z), 0.f);
    r.w = fmaxf(fmaf(d, a0.w, bb.w), 0.f);

    if (!POOL) {
        __nv_bfloat162 o0 = __float22bfloat162_rn(make_float2(r.x, r.y));
        __nv_bfloat162 o1 = __float22bfloat162_rn(make_float2(r.z, r.w));
        uint2 ov;
        ov.x = *(const uint32_t*)&o0;
        ov.y = *(const uint32_t*)&o1;
        ((uint2*)g_h2)[node * 32 + lane] = ov;
    } else {
        ((float4*)s_row[w])[lane] = r;
        if (lane == 0) s_b[w] = batch[node];
        __syncthreads();
        if (threadIdx.x < 128) {
            int col = threadIdx.x;
            float acc = 0.f;
            int cnt = 0;
            int cur = s_b[0];
            #pragma unroll
            for (int n = 0; n < 8; n++) {
                int g = s_b[n];
                if (g != cur) {
                    atomicAdd(&g_pool[cur * HID + col], acc);
                    if (col == 0) atomicAdd(&g_cnt[cur], cnt);
                    acc = 0.f; cnt = 0; cur = g;
                }
                acc += s_row[n][col];
                cnt++;
            }
            atomicAdd(&g_pool[cur * HID + col], acc);
            if (col == 0) atomicAdd(&g_cnt[cur], cnt);
        }
    }
}

// ---------------- output heads (mean-div fused) ----------------
__global__ void k_heads(const float* __restrict__ Wmf, const float* __restrict__ bmf,
                        const float* __restrict__ Wbp, const float* __restrict__ bbp,
                        const float* __restrict__ Wcc, const float* __restrict__ bcc,
                        float* __restrict__ out) {
    const int TOT = OUT_MF + OUT_BP + OUT_CC;
    int idx = blockIdx.x * blockDim.x + threadIdx.x;
    if (idx >= N_GRAPHS * TOT) return;
    int g = idx / TOT;
    int c = idx % TOT;

    const float* W;
    const float* b;
    float* o;
    int od, cc;
    if (c < OUT_MF) {
        W = Wmf; b = bmf; od = OUT_MF; cc = c;
        o = out;
    } else if (c < OUT_MF + OUT_BP) {
        W = Wbp; b = bbp; od = OUT_BP; cc = c - OUT_MF;
        o = out + N_GRAPHS * OUT_MF;
    } else {
        W = Wcc; b = bcc; od = OUT_CC; cc = c - OUT_MF - OUT_BP;
        o = out + N_GRAPHS * (OUT_MF + OUT_BP);
    }

    const float* p = g_pool + g * HID;
    float inv = 1.0f / fmaxf((float)g_cnt[g], 1.0f);
    float acc = 0.f;
    #pragma unroll 8
    for (int k = 0; k < HID; k++) acc = fmaf(p[k], W[k * od + cc], acc);
    o[g * od + cc] = fmaf(acc, inv, b[cc]);
}

// ---------------- launch (single stream, capture-safe) ----------------
extern "C" void kernel_launch(void* const* d_in, const int* in_sizes, int n_in,
                              void* d_out, int out_size) {
    const float* x    = (const float*)d_in[0];
    const int*   ei   = (const int*)d_in[1];
    const int*   bat  = (const int*)d_in[2];
    const float* W1   = (const float*)d_in[3];
    const float* b1   = (const float*)d_in[4];
    const float* W2   = (const float*)d_in[5];
    const float* b2   = (const float*)d_in[6];
    const float* Wmf  = (const float*)d_in[7];
    const float* bmf  = (const float*)d_in[8];
    const float* Wbp  = (const float*)d_in[9];
    const float* bbp  = (const float*)d_in[10];
    const float* Wcc  = (const float*)d_in[11];
    const float* bcc  = (const float*)d_in[12];
    float* out = (float*)d_out;

    const int* src = ei;
    const int* dst = ei + N_EDGES;

    // CSR prep (count captures per-edge rank; fused scan)
    k_zero<<<512, 256>>>();
    k_count<<<EBLK8, 256>>>(dst);
    k_scan<<<NPART, 1024>>>();

    // GEMM1 (dis epilogue, writes scaled bf16 hs) || atomic-free CSR fill
    k_mega<<<GEMM_BLOCKS + EBLK4, 256>>>(x, W1, src, dst);

    // layer 1 aggregation (writes bf16 h2)
    k_agg<false><<<AGG_BLOCKS, 256>>>(b1, bat);

    // layer 2
    k_gemm2<<<GEMM_BLOCKS, 256>>>(W2);
    k_agg<true><<<AGG_BLOCKS, 256>>>(b2, bat);           // agg + fused pooling

    k_heads<<<(N_GRAPHS * (OUT_MF + OUT_BP + OUT_CC) + 255) / 256, 256>>>(
        Wmf, bmf, Wbp, bbp, Wcc, bcc, out);
}